// round 1
// baseline (speedup 1.0000x reference)
#include <cuda_runtime.h>
#include <cuda_bf16.h>
#include <math.h>

// Scratch (allowed: __device__ globals, no dynamic allocation)
__device__ float g_xn[4 * 1024 * 1024];     // normalized x     [B,C,T]
__device__ float g_qkv[4 * 3072 * 1024];    // qkv projections  [B,3C,T]
__device__ float g_attn[4 * 1024 * 1024];   // attention output [B,C,T]

// ---------------------------------------------------------------------------
// GroupNorm: one block per (batch, group). 32 channels x 1024 T per group.
// ---------------------------------------------------------------------------
__global__ void gn_kernel(const float* __restrict__ x, const float* __restrict__ w,
                          const float* __restrict__ b, float* __restrict__ xn) {
    int batch = blockIdx.x >> 5;
    int g = blockIdx.x & 31;
    const float* xp = x + ((size_t)batch * 1024 + g * 32) * 1024;
    float* xo = xn + ((size_t)batch * 1024 + g * 32) * 1024;

    float s = 0.f, ss = 0.f;
    for (int i = threadIdx.x; i < 32768; i += 256) {
        float v = xp[i];
        s += v;
        ss += v * v;
    }
    // warp reduce
    #pragma unroll
    for (int o = 16; o; o >>= 1) {
        s  += __shfl_xor_sync(0xffffffffu, s, o);
        ss += __shfl_xor_sync(0xffffffffu, ss, o);
    }
    __shared__ float red[18];
    int warp = threadIdx.x >> 5, lane = threadIdx.x & 31;
    if (lane == 0) { red[warp] = s; red[warp + 8] = ss; }
    __syncthreads();
    if (threadIdx.x == 0) {
        float ts = 0.f, tss = 0.f;
        #pragma unroll
        for (int i = 0; i < 8; i++) { ts += red[i]; tss += red[i + 8]; }
        float mu = ts * (1.f / 32768.f);
        float var = tss * (1.f / 32768.f) - mu * mu;
        red[16] = mu;
        red[17] = rsqrtf(var + 1e-5f);
    }
    __syncthreads();
    float mu = red[16], inv = red[17];
    for (int i = threadIdx.x; i < 32768; i += 256) {
        int c = g * 32 + (i >> 10);
        xo[i] = (xp[i] - mu) * inv * w[c] + b[c];
    }
}

// ---------------------------------------------------------------------------
// SGEMM: out[b,o,t] = sum_c W[o,c] * X[b,c,t] + bias[o] (+ residual R)
// 64x64 output tile per block, 256 threads, 4x4 per thread, k-tile 16.
// ---------------------------------------------------------------------------
__global__ void sgemm_kernel(const float* __restrict__ W, const float* __restrict__ X,
                             const float* __restrict__ bias, const float* __restrict__ R,
                             float* __restrict__ out, int O, int Kdim) {
    __shared__ float Ws[16][68];   // [k][o], padded for transpose-store + float4 reads
    __shared__ float Xs[16][64];   // [k][t]

    int tid = threadIdx.x;
    int o0 = blockIdx.y * 64, t0 = blockIdx.x * 64;
    const float* Xb = X + (size_t)blockIdx.z * Kdim * 1024;

    float acc[4][4];
    #pragma unroll
    for (int u = 0; u < 4; u++)
        #pragma unroll
        for (int v = 0; v < 4; v++) acc[u][v] = 0.f;

    int tx = tid & 15, ty = tid >> 4;
    int lw_k = tid & 15, lw_o = tid >> 4;   // W: k-fast for coalesced global
    int lx_t = tid & 63, lx_k = tid >> 6;   // X: t-fast for coalesced global

    for (int k0 = 0; k0 < Kdim; k0 += 16) {
        #pragma unroll
        for (int r = 0; r < 4; r++)
            Ws[lw_k][lw_o + r * 16] = W[(size_t)(o0 + lw_o + r * 16) * Kdim + k0 + lw_k];
        #pragma unroll
        for (int r = 0; r < 4; r++)
            Xs[lx_k + r * 4][lx_t] = Xb[(size_t)(k0 + lx_k + r * 4) * 1024 + t0 + lx_t];
        __syncthreads();

        #pragma unroll
        for (int kk = 0; kk < 16; kk++) {
            float4 a4 = *(const float4*)&Ws[kk][ty * 4];
            float4 b4 = *(const float4*)&Xs[kk][tx * 4];
            acc[0][0] += a4.x * b4.x; acc[0][1] += a4.x * b4.y; acc[0][2] += a4.x * b4.z; acc[0][3] += a4.x * b4.w;
            acc[1][0] += a4.y * b4.x; acc[1][1] += a4.y * b4.y; acc[1][2] += a4.y * b4.z; acc[1][3] += a4.y * b4.w;
            acc[2][0] += a4.z * b4.x; acc[2][1] += a4.z * b4.y; acc[2][2] += a4.z * b4.z; acc[2][3] += a4.z * b4.w;
            acc[3][0] += a4.w * b4.x; acc[3][1] += a4.w * b4.y; acc[3][2] += a4.w * b4.z; acc[3][3] += a4.w * b4.w;
        }
        __syncthreads();
    }

    #pragma unroll
    for (int u = 0; u < 4; u++) {
        int o = o0 + ty * 4 + u;
        float bv = bias[o];
        size_t base = ((size_t)blockIdx.z * O + o) * 1024 + t0 + tx * 4;
        #pragma unroll
        for (int v = 0; v < 4; v++) {
            float r = acc[u][v] + bv;
            if (R) r += R[base + v];
            out[base + v] = r;
        }
    }
}

// ---------------------------------------------------------------------------
// Flash attention per (b,h): tiles of 64 queries x 64 keys, ch=64, T=1024.
// qkv layout: [b, h*192 + part*64 + c, t]; scale^2 = 1/8 applied to scores.
// ---------------------------------------------------------------------------
#define ATTN_SMEM_BYTES ((64 * 64 + 64 * 68 + 64 * 68 + 128) * 4)

__global__ void attn_kernel(const float* __restrict__ qkv, float* __restrict__ out) {
    int bh = blockIdx.y;
    int b = bh >> 4, h = bh & 15;
    int t0 = blockIdx.x * 64;

    extern __shared__ float sm[];
    float* Qs = sm;                 // [c(64)][i(64)]
    float* Ks = Qs + 64 * 64;       // [c(64)][j(68 pad)]  (reused for V)
    float* Ss = Ks + 64 * 68;       // [i(64)][j(68 pad)]
    float* alpha_s = Ss + 64 * 68;  // [64]
    float* l_s = alpha_s + 64;      // [64]

    const float* qp = qkv + ((size_t)b * 3072 + h * 192) * 1024;
    const float* kp = qp + 64 * 1024;
    const float* vp = qp + 128 * 1024;

    int tid = threadIdx.x;
    int lane_i = tid & 63;    // query/key column index this thread owns
    int grp = tid >> 6;       // 0..3

    // Load Q tile
    #pragma unroll
    for (int r = 0; r < 16; r++) {
        int c = grp * 16 + r;
        Qs[c * 64 + lane_i] = qp[(size_t)c * 1024 + t0 + lane_i];
    }

    float acc[16];
    #pragma unroll
    for (int r = 0; r < 16; r++) acc[r] = 0.f;
    float m_run = -1e30f, l_run = 0.f;   // valid for softmax-role mapping below
    int row = tid >> 2, sub = tid & 3;   // 4 threads per query row
    __syncthreads();

    for (int s0 = 0; s0 < 1024; s0 += 64) {
        // --- load K tile ---
        #pragma unroll
        for (int r = 0; r < 16; r++) {
            int c = grp * 16 + r;
            Ks[c * 68 + lane_i] = kp[(size_t)c * 1024 + s0 + lane_i];
        }
        __syncthreads();

        // --- S = (Q^T K) * 1/8 : thread handles column j=lane_i, rows grp*16..+15 ---
        {
            float sacc[16];
            #pragma unroll
            for (int r = 0; r < 16; r++) sacc[r] = 0.f;
            #pragma unroll 16
            for (int c = 0; c < 64; c++) {
                float kv = Ks[c * 68 + lane_i];
                #pragma unroll
                for (int r4 = 0; r4 < 4; r4++) {
                    float4 q4 = *(const float4*)&Qs[c * 64 + grp * 16 + r4 * 4];
                    sacc[r4 * 4 + 0] += q4.x * kv;
                    sacc[r4 * 4 + 1] += q4.y * kv;
                    sacc[r4 * 4 + 2] += q4.z * kv;
                    sacc[r4 * 4 + 3] += q4.w * kv;
                }
            }
            #pragma unroll
            for (int r = 0; r < 16; r++)
                Ss[(grp * 16 + r) * 68 + lane_i] = sacc[r] * 0.125f;
        }
        __syncthreads();

        // --- online softmax: 4 threads per row, 16 cols each ---
        {
            float mx = -1e30f;
            #pragma unroll
            for (int j = 0; j < 16; j++)
                mx = fmaxf(mx, Ss[row * 68 + sub * 16 + j]);
            mx = fmaxf(mx, __shfl_xor_sync(0xffffffffu, mx, 1));
            mx = fmaxf(mx, __shfl_xor_sync(0xffffffffu, mx, 2));
            float m_new = fmaxf(m_run, mx);
            float alpha = __expf(m_run - m_new);
            float ps = 0.f;
            #pragma unroll
            for (int j = 0; j < 16; j++) {
                float p = __expf(Ss[row * 68 + sub * 16 + j] - m_new);
                Ss[row * 68 + sub * 16 + j] = p;
                ps += p;
            }
            ps += __shfl_xor_sync(0xffffffffu, ps, 1);
            ps += __shfl_xor_sync(0xffffffffu, ps, 2);
            l_run = l_run * alpha + ps;
            m_run = m_new;
            if (sub == 0) { alpha_s[row] = alpha; l_s[row] = l_run; }
        }
        __syncthreads();

        // --- load V tile into Ks buffer ---
        #pragma unroll
        for (int r = 0; r < 16; r++) {
            int c = grp * 16 + r;
            Ks[c * 68 + lane_i] = vp[(size_t)c * 1024 + s0 + lane_i];
        }
        __syncthreads();

        // --- O[c][i] = O*alpha + P V^T : thread owns i=lane_i, c = grp*16+r ---
        {
            float al = alpha_s[lane_i];
            #pragma unroll
            for (int r = 0; r < 16; r++) acc[r] *= al;
            #pragma unroll
            for (int j = 0; j < 64; j += 4) {
                float4 p4 = *(const float4*)&Ss[lane_i * 68 + j];
                #pragma unroll
                for (int r = 0; r < 16; r++) {
                    float4 v4 = *(const float4*)&Ks[(grp * 16 + r) * 68 + j];
                    acc[r] += p4.x * v4.x + p4.y * v4.y + p4.z * v4.z + p4.w * v4.w;
                }
            }
        }
        __syncthreads();
    }

    float linv = 1.f / l_s[lane_i];
    #pragma unroll
    for (int r = 0; r < 16; r++) {
        int c = grp * 16 + r;
        out[((size_t)b * 1024 + h * 64 + c) * 1024 + t0 + lane_i] = acc[r] * linv;
    }
}

// ---------------------------------------------------------------------------
extern "C" void kernel_launch(void* const* d_in, const int* in_sizes, int n_in,
                              void* d_out, int out_size) {
    const float* x      = (const float*)d_in[0];
    const float* nw     = (const float*)d_in[1];
    const float* nb     = (const float*)d_in[2];
    const float* qkv_w  = (const float*)d_in[3];
    const float* qkv_b  = (const float*)d_in[4];
    const float* proj_w = (const float*)d_in[5];
    const float* proj_b = (const float*)d_in[6];
    float* out = (float*)d_out;

    float *xn, *qkv, *attn;
    cudaGetSymbolAddress((void**)&xn,   g_xn);
    cudaGetSymbolAddress((void**)&qkv,  g_qkv);
    cudaGetSymbolAddress((void**)&attn, g_attn);

    // 1. GroupNorm
    gn_kernel<<<128, 256>>>(x, nw, nb, xn);

    // 2. QKV projection: [3072,1024] x [1024,1024] per batch
    sgemm_kernel<<<dim3(16, 48, 4), 256>>>(qkv_w, xn, qkv_b, nullptr, qkv, 3072, 1024);

    // 3. Attention
    cudaFuncSetAttribute(attn_kernel, cudaFuncAttributeMaxDynamicSharedMemorySize,
                         ATTN_SMEM_BYTES);
    attn_kernel<<<dim3(16, 64), 256, ATTN_SMEM_BYTES>>>(qkv, attn);

    // 4. Output projection + bias + residual
    sgemm_kernel<<<dim3(16, 16, 4), 256>>>(proj_w, attn, proj_b, x, out, 1024, 1024);
}

// round 3
// speedup vs baseline: 1.5153x; 1.5153x over previous
#include <cuda_runtime.h>
#include <cuda_bf16.h>
#include <math.h>
#include <stdint.h>

// ---------------------------------------------------------------------------
// Scratch (device globals; no dynamic allocation allowed)
// ---------------------------------------------------------------------------
__device__ float g_xn[4 * 1024 * 1024];     // normalized x     [B,C,T]
__device__ float g_qkv[4 * 3072 * 1024];    // qkv projections  [B,3C,T]
__device__ float g_attn[4 * 1024 * 1024];   // attention output [B,C,T]

// ---------------------------------------------------------------------------
// helpers
// ---------------------------------------------------------------------------
__device__ __forceinline__ uint32_t smem_u32(const void* p) {
    uint32_t a;
    asm("{ .reg .u64 t; cvta.to.shared.u64 t, %1; cvt.u32.u64 %0, t; }" : "=r"(a) : "l"(p));
    return a;
}
__device__ __forceinline__ uint32_t tf32u(float x) {
    uint32_t y; asm("cvt.rna.tf32.f32 %0, %1;" : "=r"(y) : "f"(x)); return y;
}
__device__ __forceinline__ void cp16(uint32_t dst, const void* src) {
    asm volatile("cp.async.cg.shared.global [%0], [%1], 16;" :: "r"(dst), "l"(src));
}
__device__ __forceinline__ void cp_commit() { asm volatile("cp.async.commit_group;"); }
__device__ __forceinline__ void cp_wait0() { asm volatile("cp.async.wait_group 0;" ::: "memory"); }
__device__ __forceinline__ void cp_wait1() { asm volatile("cp.async.wait_group 1;" ::: "memory"); }

__device__ __forceinline__ void mma_tf32(float* c, const uint32_t* a, const uint32_t* b) {
    asm volatile(
        "mma.sync.aligned.m16n8k8.row.col.f32.tf32.tf32.f32 "
        "{%0,%1,%2,%3}, {%4,%5,%6,%7}, {%8,%9}, {%0,%1,%2,%3};"
        : "+f"(c[0]), "+f"(c[1]), "+f"(c[2]), "+f"(c[3])
        : "r"(a[0]), "r"(a[1]), "r"(a[2]), "r"(a[3]), "r"(b[0]), "r"(b[1]));
}

// ---------------------------------------------------------------------------
// TF32 tensor-core GEMM via mma.sync:
//   out[z,o,t] = sum_k W[o,k] * X[z,k,t] + bias[o] (+ R[z,o,t])
// CTA tile 128(o) x 128(t), K-tile 32, double-buffered cp.async.
// 256 threads = 8 warps in 4(m) x 2(n); warp tile 32 x 64.
// ---------------------------------------------------------------------------
#define WPAD 36
#define XPAD 132
#define GEMM_SMEM ((2 * 128 * WPAD + 2 * 32 * XPAD) * 4)

__global__ __launch_bounds__(256) void mma_gemm(const float* __restrict__ W,
                                                const float* __restrict__ X,
                                                const float* __restrict__ bias,
                                                const float* __restrict__ R,
                                                float* __restrict__ out, int O) {
    extern __shared__ float sm[];
    float* sW = sm;                       // [2][128][WPAD]
    float* sX = sm + 2 * 128 * WPAD;      // [2][32][XPAD]

    const int tid = threadIdx.x;
    const int wid = tid >> 5, lane = tid & 31;
    const int gid = lane >> 2, tg = lane & 3;
    const int warp_m = (wid & 3) * 32, warp_n = (wid >> 2) * 64;

    const int t0 = blockIdx.x * 128, o0 = blockIdx.y * 128, z = blockIdx.z;
    const float* Xb = X + (size_t)z * 1024 * 1024;

    // load maps: W tile 128 rows x 8 float4; X tile 32 rows x 32 float4; 4 each
    const int w_row = tid >> 1;                  // with i*? -> use id = tid*... recompute below
    (void)w_row;

    float c[2][8][4];
#pragma unroll
    for (int mt = 0; mt < 2; mt++)
#pragma unroll
        for (int nt = 0; nt < 8; nt++)
#pragma unroll
            for (int e = 0; e < 4; e++) c[mt][nt][e] = 0.f;

    uint32_t aW = smem_u32(sW), aX = smem_u32(sX);

    // issue loads for buffer `buf`, k-tile index kt
    auto issue = [&](int buf, int kt) {
        const int k0 = kt * 32;
        uint32_t bW = aW + (uint32_t)(buf * 128 * WPAD * 4);
        uint32_t bX = aX + (uint32_t)(buf * 32 * XPAD * 4);
#pragma unroll
        for (int i = 0; i < 4; i++) {
            int id = tid * 4 + i;              // 0..1023
            int row = id >> 3, kv = id & 7;    // W: row 0..127, float4 idx 0..7
            cp16(bW + (uint32_t)((row * WPAD + kv * 4) * 4),
                 W + (size_t)(o0 + row) * 1024 + k0 + kv * 4);
        }
#pragma unroll
        for (int i = 0; i < 4; i++) {
            int id = tid * 4 + i;
            int krow = id >> 5, tv = id & 31;  // X: k 0..31, float4 idx 0..31
            cp16(bX + (uint32_t)((krow * XPAD + tv * 4) * 4),
                 Xb + (size_t)(k0 + krow) * 1024 + t0 + tv * 4);
        }
        cp_commit();
    };

    issue(0, 0);

    for (int kt = 0; kt < 32; kt++) {
        const int buf = kt & 1;
        if (kt + 1 < 32) {
            issue(buf ^ 1, kt + 1);
            cp_wait1();
        } else {
            cp_wait0();
        }
        __syncthreads();

        const float* wb = sW + buf * 128 * WPAD;
        const float* xb = sX + buf * 32 * XPAD;

#pragma unroll
        for (int ks = 0; ks < 4; ks++) {
            const int kk = ks * 8;
            uint32_t af[2][4];
#pragma unroll
            for (int mt = 0; mt < 2; mt++) {
                const float* wr = wb + (warp_m + mt * 16 + gid) * WPAD + kk + tg;
                af[mt][0] = tf32u(wr[0]);
                af[mt][1] = tf32u(wr[8 * WPAD]);
                af[mt][2] = tf32u(wr[4]);
                af[mt][3] = tf32u(wr[8 * WPAD + 4]);
            }
            uint32_t bf[8][2];
#pragma unroll
            for (int nt = 0; nt < 8; nt++) {
                const float* xr = xb + (kk + tg) * XPAD + warp_n + nt * 8 + gid;
                bf[nt][0] = tf32u(xr[0]);
                bf[nt][1] = tf32u(xr[4 * XPAD]);
            }
#pragma unroll
            for (int mt = 0; mt < 2; mt++)
#pragma unroll
                for (int nt = 0; nt < 8; nt++)
                    mma_tf32(c[mt][nt], af[mt], bf[nt]);
        }
        __syncthreads();
    }

    // epilogue: C[mt][nt]: rows gid / gid+8, cols tg*2, tg*2+1
#pragma unroll
    for (int mt = 0; mt < 2; mt++) {
#pragma unroll
        for (int half = 0; half < 2; half++) {
            int o = o0 + warp_m + mt * 16 + gid + half * 8;
            float bv = bias[o];
            size_t rowbase = ((size_t)z * O + o) * 1024;
#pragma unroll
            for (int nt = 0; nt < 8; nt++) {
                int t = t0 + warp_n + nt * 8 + tg * 2;
                float2 v;
                v.x = c[mt][nt][half * 2 + 0] + bv;
                v.y = c[mt][nt][half * 2 + 1] + bv;
                if (R) {
                    float2 rr = *(const float2*)(R + rowbase + t);
                    v.x += rr.x; v.y += rr.y;
                }
                *(float2*)(out + rowbase + t) = v;
            }
        }
    }
}

// ---------------------------------------------------------------------------
// GroupNorm: one block per (batch, group). 32 channels x 1024 T per group.
// ---------------------------------------------------------------------------
__global__ void gn_kernel(const float* __restrict__ x, const float* __restrict__ w,
                          const float* __restrict__ b, float* __restrict__ xn) {
    int batch = blockIdx.x >> 5;
    int g = blockIdx.x & 31;
    const float* xp = x + ((size_t)batch * 1024 + g * 32) * 1024;
    float* xo = xn + ((size_t)batch * 1024 + g * 32) * 1024;

    float s = 0.f, ss = 0.f;
    for (int i = threadIdx.x; i < 32768; i += 256) {
        float v = xp[i];
        s += v; ss += v * v;
    }
#pragma unroll
    for (int o = 16; o; o >>= 1) {
        s  += __shfl_xor_sync(0xffffffffu, s, o);
        ss += __shfl_xor_sync(0xffffffffu, ss, o);
    }
    __shared__ float red[18];
    int warp = threadIdx.x >> 5, lane = threadIdx.x & 31;
    if (lane == 0) { red[warp] = s; red[warp + 8] = ss; }
    __syncthreads();
    if (threadIdx.x == 0) {
        float ts = 0.f, tss = 0.f;
#pragma unroll
        for (int i = 0; i < 8; i++) { ts += red[i]; tss += red[i + 8]; }
        float mu = ts * (1.f / 32768.f);
        float var = tss * (1.f / 32768.f) - mu * mu;
        red[16] = mu;
        red[17] = rsqrtf(var + 1e-5f);
    }
    __syncthreads();
    float mu = red[16], inv = red[17];
    for (int i = threadIdx.x; i < 32768; i += 256) {
        int c = g * 32 + (i >> 10);
        xo[i] = (xp[i] - mu) * inv * w[c] + b[c];
    }
}

// ---------------------------------------------------------------------------
// Flash attention per (b,h): tiles of 64 queries x 64 keys, ch=64, T=1024.
// ---------------------------------------------------------------------------
#define ATTN_SMEM_BYTES ((64 * 64 + 64 * 68 + 64 * 68 + 128) * 4)

__global__ void attn_kernel(const float* __restrict__ qkv, float* __restrict__ out) {
    int bh = blockIdx.y;
    int b = bh >> 4, h = bh & 15;
    int t0 = blockIdx.x * 64;

    extern __shared__ float sm[];
    float* Qs = sm;
    float* Ks = Qs + 64 * 64;
    float* Ss = Ks + 64 * 68;
    float* alpha_s = Ss + 64 * 68;
    float* l_s = alpha_s + 64;

    const float* qp = qkv + ((size_t)b * 3072 + h * 192) * 1024;
    const float* kp = qp + 64 * 1024;
    const float* vp = qp + 128 * 1024;

    int tid = threadIdx.x;
    int lane_i = tid & 63;
    int grp = tid >> 6;

#pragma unroll
    for (int r = 0; r < 16; r++) {
        int c = grp * 16 + r;
        Qs[c * 64 + lane_i] = qp[(size_t)c * 1024 + t0 + lane_i];
    }

    float acc[16];
#pragma unroll
    for (int r = 0; r < 16; r++) acc[r] = 0.f;
    float m_run = -1e30f, l_run = 0.f;
    int row = tid >> 2, sub = tid & 3;
    __syncthreads();

    for (int s0 = 0; s0 < 1024; s0 += 64) {
#pragma unroll
        for (int r = 0; r < 16; r++) {
            int c = grp * 16 + r;
            Ks[c * 68 + lane_i] = kp[(size_t)c * 1024 + s0 + lane_i];
        }
        __syncthreads();

        {
            float sacc[16];
#pragma unroll
            for (int r = 0; r < 16; r++) sacc[r] = 0.f;
#pragma unroll 16
            for (int c = 0; c < 64; c++) {
                float kv = Ks[c * 68 + lane_i];
#pragma unroll
                for (int r4 = 0; r4 < 4; r4++) {
                    float4 q4 = *(const float4*)&Qs[c * 64 + grp * 16 + r4 * 4];
                    sacc[r4 * 4 + 0] += q4.x * kv;
                    sacc[r4 * 4 + 1] += q4.y * kv;
                    sacc[r4 * 4 + 2] += q4.z * kv;
                    sacc[r4 * 4 + 3] += q4.w * kv;
                }
            }
#pragma unroll
            for (int r = 0; r < 16; r++)
                Ss[(grp * 16 + r) * 68 + lane_i] = sacc[r] * 0.125f;
        }
        __syncthreads();

        {
            float mx = -1e30f;
#pragma unroll
            for (int j = 0; j < 16; j++)
                mx = fmaxf(mx, Ss[row * 68 + sub * 16 + j]);
            mx = fmaxf(mx, __shfl_xor_sync(0xffffffffu, mx, 1));
            mx = fmaxf(mx, __shfl_xor_sync(0xffffffffu, mx, 2));
            float m_new = fmaxf(m_run, mx);
            float alpha = __expf(m_run - m_new);
            float ps = 0.f;
#pragma unroll
            for (int j = 0; j < 16; j++) {
                float p = __expf(Ss[row * 68 + sub * 16 + j] - m_new);
                Ss[row * 68 + sub * 16 + j] = p;
                ps += p;
            }
            ps += __shfl_xor_sync(0xffffffffu, ps, 1);
            ps += __shfl_xor_sync(0xffffffffu, ps, 2);
            l_run = l_run * alpha + ps;
            m_run = m_new;
            if (sub == 0) { alpha_s[row] = alpha; l_s[row] = l_run; }
        }
        __syncthreads();

#pragma unroll
        for (int r = 0; r < 16; r++) {
            int c = grp * 16 + r;
            Ks[c * 68 + lane_i] = vp[(size_t)c * 1024 + s0 + lane_i];
        }
        __syncthreads();

        {
            float al = alpha_s[lane_i];
#pragma unroll
            for (int r = 0; r < 16; r++) acc[r] *= al;
#pragma unroll
            for (int j = 0; j < 64; j += 4) {
                float4 p4 = *(const float4*)&Ss[lane_i * 68 + j];
#pragma unroll
                for (int r = 0; r < 16; r++) {
                    float4 v4 = *(const float4*)&Ks[(grp * 16 + r) * 68 + j];
                    acc[r] += p4.x * v4.x + p4.y * v4.y + p4.z * v4.z + p4.w * v4.w;
                }
            }
        }
        __syncthreads();
    }

    float linv = 1.f / l_s[lane_i];
#pragma unroll
    for (int r = 0; r < 16; r++) {
        int c = grp * 16 + r;
        out[((size_t)b * 1024 + h * 64 + c) * 1024 + t0 + lane_i] = acc[r] * linv;
    }
}

// ---------------------------------------------------------------------------
extern "C" void kernel_launch(void* const* d_in, const int* in_sizes, int n_in,
                              void* d_out, int out_size) {
    const float* x      = (const float*)d_in[0];
    const float* nw     = (const float*)d_in[1];
    const float* nb     = (const float*)d_in[2];
    const float* qkv_w  = (const float*)d_in[3];
    const float* qkv_b  = (const float*)d_in[4];
    const float* proj_w = (const float*)d_in[5];
    const float* proj_b = (const float*)d_in[6];
    float* out = (float*)d_out;

    float *xn, *qkv, *attn;
    cudaGetSymbolAddress((void**)&xn,   g_xn);
    cudaGetSymbolAddress((void**)&qkv,  g_qkv);
    cudaGetSymbolAddress((void**)&attn, g_attn);

    // 1. GroupNorm
    gn_kernel<<<128, 256>>>(x, nw, nb, xn);

    // 2. QKV projection (tf32 mma.sync): [3072,1024] x [1024,1024] per batch
    cudaFuncSetAttribute(mma_gemm, cudaFuncAttributeMaxDynamicSharedMemorySize, GEMM_SMEM);
    mma_gemm<<<dim3(8, 24, 4), 256, GEMM_SMEM>>>(qkv_w, xn, qkv_b, nullptr, qkv, 3072);

    // 3. Attention (fp32 flash)
    cudaFuncSetAttribute(attn_kernel, cudaFuncAttributeMaxDynamicSharedMemorySize,
                         ATTN_SMEM_BYTES);
    attn_kernel<<<dim3(16, 64), 256, ATTN_SMEM_BYTES>>>(qkv, attn);

    // 4. Output projection + bias + residual (tf32 mma.sync)
    mma_gemm<<<dim3(8, 8, 4), 256, GEMM_SMEM>>>(proj_w, attn, proj_b, x, out, 1024);
}

// round 4
// speedup vs baseline: 2.2234x; 1.4674x over previous
#include <cuda_runtime.h>
#include <cuda_bf16.h>
#include <math.h>
#include <stdint.h>

// ---------------------------------------------------------------------------
// Scratch (device globals; no dynamic allocation allowed)
// ---------------------------------------------------------------------------
__device__ float g_xn[4 * 1024 * 1024];     // normalized x     [B,C,T]
__device__ float g_qkv[4 * 3072 * 1024];    // qkv projections  [B,3C,T]
__device__ float g_attn[4 * 1024 * 1024];   // attention output [B,C,T]

// ---------------------------------------------------------------------------
// helpers
// ---------------------------------------------------------------------------
__device__ __forceinline__ uint32_t smem_u32(const void* p) {
    uint32_t a;
    asm("{ .reg .u64 t; cvta.to.shared.u64 t, %1; cvt.u32.u64 %0, t; }" : "=r"(a) : "l"(p));
    return a;
}
__device__ __forceinline__ uint32_t tf32u(float x) {
    uint32_t y; asm("cvt.rna.tf32.f32 %0, %1;" : "=r"(y) : "f"(x)); return y;
}
__device__ __forceinline__ float tf32f(float x) {
    return __uint_as_float(tf32u(x));
}
__device__ __forceinline__ void cp16(uint32_t dst, const void* src) {
    asm volatile("cp.async.cg.shared.global [%0], [%1], 16;" :: "r"(dst), "l"(src));
}
__device__ __forceinline__ void cp_commit() { asm volatile("cp.async.commit_group;"); }
__device__ __forceinline__ void cp_wait0() { asm volatile("cp.async.wait_group 0;" ::: "memory"); }
__device__ __forceinline__ void cp_wait1() { asm volatile("cp.async.wait_group 1;" ::: "memory"); }

__device__ __forceinline__ void mma_tf32(float* c, const uint32_t* a, const uint32_t* b) {
    asm volatile(
        "mma.sync.aligned.m16n8k8.row.col.f32.tf32.tf32.f32 "
        "{%0,%1,%2,%3}, {%4,%5,%6,%7}, {%8,%9}, {%0,%1,%2,%3};"
        : "+f"(c[0]), "+f"(c[1]), "+f"(c[2]), "+f"(c[3])
        : "r"(a[0]), "r"(a[1]), "r"(a[2]), "r"(a[3]), "r"(b[0]), "r"(b[1]));
}

// ---------------------------------------------------------------------------
// TF32 tensor-core GEMM via mma.sync:
//   out[z,o,t] = sum_k W[o,k] * X[z,k,t] + bias[o] (+ R[z,o,t])
// ---------------------------------------------------------------------------
#define WPAD 36
#define XPAD 132
#define GEMM_SMEM ((2 * 128 * WPAD + 2 * 32 * XPAD) * 4)

__global__ __launch_bounds__(256) void mma_gemm(const float* __restrict__ W,
                                                const float* __restrict__ X,
                                                const float* __restrict__ bias,
                                                const float* __restrict__ R,
                                                float* __restrict__ out, int O) {
    extern __shared__ float sm[];
    float* sW = sm;                       // [2][128][WPAD]
    float* sX = sm + 2 * 128 * WPAD;      // [2][32][XPAD]

    const int tid = threadIdx.x;
    const int wid = tid >> 5, lane = tid & 31;
    const int gid = lane >> 2, tg = lane & 3;
    const int warp_m = (wid & 3) * 32, warp_n = (wid >> 2) * 64;

    const int t0 = blockIdx.x * 128, o0 = blockIdx.y * 128, z = blockIdx.z;
    const float* Xb = X + (size_t)z * 1024 * 1024;

    float c[2][8][4];
#pragma unroll
    for (int mt = 0; mt < 2; mt++)
#pragma unroll
        for (int nt = 0; nt < 8; nt++)
#pragma unroll
            for (int e = 0; e < 4; e++) c[mt][nt][e] = 0.f;

    uint32_t aW = smem_u32(sW), aX = smem_u32(sX);

    auto issue = [&](int buf, int kt) {
        const int k0 = kt * 32;
        uint32_t bW = aW + (uint32_t)(buf * 128 * WPAD * 4);
        uint32_t bX = aX + (uint32_t)(buf * 32 * XPAD * 4);
#pragma unroll
        for (int i = 0; i < 4; i++) {
            int id = tid * 4 + i;
            int row = id >> 3, kv = id & 7;
            cp16(bW + (uint32_t)((row * WPAD + kv * 4) * 4),
                 W + (size_t)(o0 + row) * 1024 + k0 + kv * 4);
        }
#pragma unroll
        for (int i = 0; i < 4; i++) {
            int id = tid * 4 + i;
            int krow = id >> 5, tv = id & 31;
            cp16(bX + (uint32_t)((krow * XPAD + tv * 4) * 4),
                 Xb + (size_t)(k0 + krow) * 1024 + t0 + tv * 4);
        }
        cp_commit();
    };

    issue(0, 0);

    for (int kt = 0; kt < 32; kt++) {
        const int buf = kt & 1;
        if (kt + 1 < 32) {
            issue(buf ^ 1, kt + 1);
            cp_wait1();
        } else {
            cp_wait0();
        }
        __syncthreads();

        const float* wb = sW + buf * 128 * WPAD;
        const float* xb = sX + buf * 32 * XPAD;

#pragma unroll
        for (int ks = 0; ks < 4; ks++) {
            const int kk = ks * 8;
            uint32_t af[2][4];
#pragma unroll
            for (int mt = 0; mt < 2; mt++) {
                const float* wr = wb + (warp_m + mt * 16 + gid) * WPAD + kk + tg;
                af[mt][0] = tf32u(wr[0]);
                af[mt][1] = tf32u(wr[8 * WPAD]);
                af[mt][2] = tf32u(wr[4]);
                af[mt][3] = tf32u(wr[8 * WPAD + 4]);
            }
            uint32_t bf[8][2];
#pragma unroll
            for (int nt = 0; nt < 8; nt++) {
                const float* xr = xb + (kk + tg) * XPAD + warp_n + nt * 8 + gid;
                bf[nt][0] = tf32u(xr[0]);
                bf[nt][1] = tf32u(xr[4 * XPAD]);
            }
#pragma unroll
            for (int mt = 0; mt < 2; mt++)
#pragma unroll
                for (int nt = 0; nt < 8; nt++)
                    mma_tf32(c[mt][nt], af[mt], bf[nt]);
        }
        __syncthreads();
    }

#pragma unroll
    for (int mt = 0; mt < 2; mt++) {
#pragma unroll
        for (int half = 0; half < 2; half++) {
            int o = o0 + warp_m + mt * 16 + gid + half * 8;
            float bv = bias[o];
            size_t rowbase = ((size_t)z * O + o) * 1024;
#pragma unroll
            for (int nt = 0; nt < 8; nt++) {
                int t = t0 + warp_n + nt * 8 + tg * 2;
                float2 v;
                v.x = c[mt][nt][half * 2 + 0] + bv;
                v.y = c[mt][nt][half * 2 + 1] + bv;
                if (R) {
                    float2 rr = *(const float2*)(R + rowbase + t);
                    v.x += rr.x; v.y += rr.y;
                }
                *(float2*)(out + rowbase + t) = v;
            }
        }
    }
}

// ---------------------------------------------------------------------------
// GroupNorm
// ---------------------------------------------------------------------------
__global__ void gn_kernel(const float* __restrict__ x, const float* __restrict__ w,
                          const float* __restrict__ b, float* __restrict__ xn) {
    int batch = blockIdx.x >> 5;
    int g = blockIdx.x & 31;
    const float* xp = x + ((size_t)batch * 1024 + g * 32) * 1024;
    float* xo = xn + ((size_t)batch * 1024 + g * 32) * 1024;

    float s = 0.f, ss = 0.f;
    for (int i = threadIdx.x; i < 32768; i += 256) {
        float v = xp[i];
        s += v; ss += v * v;
    }
#pragma unroll
    for (int o = 16; o; o >>= 1) {
        s  += __shfl_xor_sync(0xffffffffu, s, o);
        ss += __shfl_xor_sync(0xffffffffu, ss, o);
    }
    __shared__ float red[18];
    int warp = threadIdx.x >> 5, lane = threadIdx.x & 31;
    if (lane == 0) { red[warp] = s; red[warp + 8] = ss; }
    __syncthreads();
    if (threadIdx.x == 0) {
        float ts = 0.f, tss = 0.f;
#pragma unroll
        for (int i = 0; i < 8; i++) { ts += red[i]; tss += red[i + 8]; }
        float mu = ts * (1.f / 32768.f);
        float var = tss * (1.f / 32768.f) - mu * mu;
        red[16] = mu;
        red[17] = rsqrtf(var + 1e-5f);
    }
    __syncthreads();
    float mu = red[16], inv = red[17];
    for (int i = threadIdx.x; i < 32768; i += 256) {
        int c = g * 32 + (i >> 10);
        xo[i] = (xp[i] - mu) * inv * w[c] + b[c];
    }
}

// ---------------------------------------------------------------------------
// Flash attention with tf32 mma.sync.
// Block = one (b,h) x 64-query tile. 256 threads, 8 warps (4 m x 2 n).
//   St[j][i] = sum_c Kt[j][c] * Qs[c][i] * 0.125   (A=Kt, B=Qs)
//   Ot[c][i] += sum_j Vs[c][j] * P[j][i]           (A=Vs, B=Ss)
// Online softmax per column i, register reductions over gid lanes.
// ---------------------------------------------------------------------------
#define APITCH 72
#define KPITCH 68
#define ATTN_SMEM ((64 * APITCH * 3 + 64 * KPITCH + 256 + 256 + 192) * 4)

__global__ __launch_bounds__(256) void attn_mma(const float* __restrict__ qkv,
                                                float* __restrict__ out) {
    extern __shared__ float sm[];
    float* Qs   = sm;                    // [64][APITCH]  (tf32 values)
    float* Kt   = Qs + 64 * APITCH;      // [64][KPITCH]  j-major (tf32)
    float* Vs   = Kt + 64 * KPITCH;      // [64][APITCH]  (tf32)
    float* Ss   = Vs + 64 * APITCH;      // [64][APITCH]  probs (tf32)
    float* pm   = Ss + 64 * APITCH;      // [4][64] partial max
    float* ps   = pm + 256;              // [4][64] partial sum
    float* marr = ps + 256;              // [64] running max
    float* lar  = marr + 64;             // [64] running sum
    float* aar  = lar + 64;              // [64] alpha

    const int bh = blockIdx.y;
    const int b = bh >> 4, h = bh & 15;
    const int t0 = blockIdx.x * 64;
    const float* qp = qkv + ((size_t)b * 3072 + h * 192) * 1024;
    const float* kp = qp + 64 * 1024;
    const float* vp = qp + 128 * 1024;

    const int tid = threadIdx.x, wid = tid >> 5, lane = tid & 31;
    const int gid = lane >> 2, tg = lane & 3;
    const int wq = wid & 3;
    const int warp_m = wq * 16;          // j rows (S) / c rows (PV)
    const int warp_n = (wid >> 2) * 32;  // i columns

    // Q tile [c][i], tf32-converted once
#pragma unroll
    for (int r = 0; r < 4; r++) {
        int id = r * 256 + tid;
        int cc = id >> 4, i4 = (id & 15) * 4;
        float4 v = *(const float4*)(qp + (size_t)cc * 1024 + t0 + i4);
        float* d = &Qs[cc * APITCH + i4];
        d[0] = tf32f(v.x); d[1] = tf32f(v.y); d[2] = tf32f(v.z); d[3] = tf32f(v.w);
    }
    if (tid < 64) { marr[tid] = -1e30f; lar[tid] = 0.f; }

    float o[4][4];
#pragma unroll
    for (int nt = 0; nt < 4; nt++)
#pragma unroll
        for (int e = 0; e < 4; e++) o[nt][e] = 0.f;

    for (int s0 = 0; s0 < 1024; s0 += 64) {
        __syncthreads();   // protect Kt/Vs/Ss from prior-tile readers

        // K tile transposed: Kt[j][c]
#pragma unroll
        for (int r = 0; r < 16; r++) {
            int id = r * 256 + tid;
            int cc = id >> 6, j = id & 63;
            Kt[j * KPITCH + cc] = tf32f(kp[(size_t)cc * 1024 + s0 + j]);
        }
        // V tile natural: Vs[c][j]
#pragma unroll
        for (int r = 0; r < 4; r++) {
            int id = r * 256 + tid;
            int cc = id >> 4, j4 = (id & 15) * 4;
            float4 v = *(const float4*)(vp + (size_t)cc * 1024 + s0 + j4);
            float* d = &Vs[cc * APITCH + j4];
            d[0] = tf32f(v.x); d[1] = tf32f(v.y); d[2] = tf32f(v.z); d[3] = tf32f(v.w);
        }
        __syncthreads();

        // ---- S = Kt * Q ----
        float sc[4][4];
#pragma unroll
        for (int nt = 0; nt < 4; nt++)
#pragma unroll
            for (int e = 0; e < 4; e++) sc[nt][e] = 0.f;

#pragma unroll
        for (int ks = 0; ks < 8; ks++) {
            int kk = ks * 8;
            uint32_t a[4];
            a[0] = __float_as_uint(Kt[(warp_m + gid) * KPITCH + kk + tg]);
            a[1] = __float_as_uint(Kt[(warp_m + gid + 8) * KPITCH + kk + tg]);
            a[2] = __float_as_uint(Kt[(warp_m + gid) * KPITCH + kk + tg + 4]);
            a[3] = __float_as_uint(Kt[(warp_m + gid + 8) * KPITCH + kk + tg + 4]);
#pragma unroll
            for (int nt = 0; nt < 4; nt++) {
                uint32_t bb[2];
                bb[0] = __float_as_uint(Qs[(kk + tg) * APITCH + warp_n + nt * 8 + gid]);
                bb[1] = __float_as_uint(Qs[(kk + tg + 4) * APITCH + warp_n + nt * 8 + gid]);
                mma_tf32(sc[nt], a, bb);
            }
        }
#pragma unroll
        for (int nt = 0; nt < 4; nt++)
#pragma unroll
            for (int e = 0; e < 4; e++) sc[nt][e] *= 0.125f;

        // per-warp column max -> pm[wq][i]
#pragma unroll
        for (int nt = 0; nt < 4; nt++) {
            float m0 = fmaxf(sc[nt][0], sc[nt][2]);
            float m1 = fmaxf(sc[nt][1], sc[nt][3]);
#pragma unroll
            for (int mk = 4; mk <= 16; mk <<= 1) {
                m0 = fmaxf(m0, __shfl_xor_sync(0xffffffffu, m0, mk));
                m1 = fmaxf(m1, __shfl_xor_sync(0xffffffffu, m1, mk));
            }
            if (gid == 0) {
                int n = warp_n + nt * 8 + tg * 2;
                pm[wq * 64 + n] = m0;
                pm[wq * 64 + n + 1] = m1;
            }
        }
        __syncthreads();

        // phase A: exp + store probs + partial sums
#pragma unroll
        for (int nt = 0; nt < 4; nt++) {
            int n = warp_n + nt * 8 + tg * 2;
#pragma unroll
            for (int e = 0; e < 2; e++) {
                int i = n + e;
                float mn = fmaxf(fmaxf(fmaxf(pm[i], pm[64 + i]),
                                       fmaxf(pm[128 + i], pm[192 + i])), marr[i]);
                float p0 = tf32f(__expf(sc[nt][e] - mn));
                float p1 = tf32f(__expf(sc[nt][e + 2] - mn));
                Ss[(warp_m + gid) * APITCH + i] = p0;
                Ss[(warp_m + gid + 8) * APITCH + i] = p1;
                float su = p0 + p1;
#pragma unroll
                for (int mk = 4; mk <= 16; mk <<= 1)
                    su += __shfl_xor_sync(0xffffffffu, su, mk);
                if (gid == 0) ps[wq * 64 + i] = su;
            }
        }
        __syncthreads();

        // phase B: designated writers update running stats
        if (wq == 0 && gid == 0) {
#pragma unroll
            for (int nt = 0; nt < 4; nt++) {
#pragma unroll
                for (int e = 0; e < 2; e++) {
                    int i = warp_n + nt * 8 + tg * 2 + e;
                    float mo = marr[i];
                    float mn = fmaxf(fmaxf(fmaxf(pm[i], pm[64 + i]),
                                           fmaxf(pm[128 + i], pm[192 + i])), mo);
                    float al = __expf(mo - mn);
                    float st = ps[i] + ps[64 + i] + ps[128 + i] + ps[192 + i];
                    lar[i] = lar[i] * al + st;
                    marr[i] = mn;
                    aar[i] = al;
                }
            }
        }
        __syncthreads();

        // ---- O = V * P ----
#pragma unroll
        for (int nt = 0; nt < 4; nt++) {
            int n = warp_n + nt * 8 + tg * 2;
            float a0 = aar[n], a1 = aar[n + 1];
            o[nt][0] *= a0; o[nt][1] *= a1; o[nt][2] *= a0; o[nt][3] *= a1;
        }
#pragma unroll
        for (int ks = 0; ks < 8; ks++) {
            int kk = ks * 8;
            uint32_t a[4];
            a[0] = __float_as_uint(Vs[(warp_m + gid) * APITCH + kk + tg]);
            a[1] = __float_as_uint(Vs[(warp_m + gid + 8) * APITCH + kk + tg]);
            a[2] = __float_as_uint(Vs[(warp_m + gid) * APITCH + kk + tg + 4]);
            a[3] = __float_as_uint(Vs[(warp_m + gid + 8) * APITCH + kk + tg + 4]);
#pragma unroll
            for (int nt = 0; nt < 4; nt++) {
                uint32_t bb[2];
                bb[0] = __float_as_uint(Ss[(kk + tg) * APITCH + warp_n + nt * 8 + gid]);
                bb[1] = __float_as_uint(Ss[(kk + tg + 4) * APITCH + warp_n + nt * 8 + gid]);
                mma_tf32(o[nt], a, bb);
            }
        }
    }
    __syncthreads();

    // normalize + write Ot[c][i] to attn[b, h*64+c, t0+i]
#pragma unroll
    for (int nt = 0; nt < 4; nt++) {
        int n = warp_n + nt * 8 + tg * 2;
        float li0 = 1.f / lar[n], li1 = 1.f / lar[n + 1];
        size_t base0 = ((size_t)b * 1024 + h * 64 + warp_m + gid) * 1024 + t0 + n;
        float2 v0 = { o[nt][0] * li0, o[nt][1] * li1 };
        *(float2*)(out + base0) = v0;
        float2 v1 = { o[nt][2] * li0, o[nt][3] * li1 };
        *(float2*)(out + base0 + 8 * 1024) = v1;
    }
}

// ---------------------------------------------------------------------------
extern "C" void kernel_launch(void* const* d_in, const int* in_sizes, int n_in,
                              void* d_out, int out_size) {
    const float* x      = (const float*)d_in[0];
    const float* nw     = (const float*)d_in[1];
    const float* nb     = (const float*)d_in[2];
    const float* qkv_w  = (const float*)d_in[3];
    const float* qkv_b  = (const float*)d_in[4];
    const float* proj_w = (const float*)d_in[5];
    const float* proj_b = (const float*)d_in[6];
    float* out = (float*)d_out;

    float *xn, *qkv, *attn;
    cudaGetSymbolAddress((void**)&xn,   g_xn);
    cudaGetSymbolAddress((void**)&qkv,  g_qkv);
    cudaGetSymbolAddress((void**)&attn, g_attn);

    // 1. GroupNorm
    gn_kernel<<<128, 256>>>(x, nw, nb, xn);

    // 2. QKV projection (tf32 mma.sync)
    cudaFuncSetAttribute(mma_gemm, cudaFuncAttributeMaxDynamicSharedMemorySize, GEMM_SMEM);
    mma_gemm<<<dim3(8, 24, 4), 256, GEMM_SMEM>>>(qkv_w, xn, qkv_b, nullptr, qkv, 3072);

    // 3. Attention (tf32 mma.sync flash)
    cudaFuncSetAttribute(attn_mma, cudaFuncAttributeMaxDynamicSharedMemorySize, ATTN_SMEM);
    attn_mma<<<dim3(16, 64), 256, ATTN_SMEM>>>(qkv, attn);

    // 4. Output projection + bias + residual (tf32 mma.sync)
    mma_gemm<<<dim3(8, 8, 4), 256, GEMM_SMEM>>>(proj_w, attn, proj_b, x, out, 1024);
}

// round 5
// speedup vs baseline: 2.4050x; 1.0817x over previous
#include <cuda_runtime.h>
#include <cuda_bf16.h>
#include <math.h>
#include <stdint.h>

// ---------------------------------------------------------------------------
// Scratch (device globals; no dynamic allocation allowed)
// ---------------------------------------------------------------------------
__device__ float g_xn[4 * 1024 * 1024];     // normalized x     [B,C,T]
__device__ float g_qkv[4 * 3072 * 1024];    // qkv projections  [B,3C,T]
__device__ float g_attn[4 * 1024 * 1024];   // attention output [B,C,T]

// ---------------------------------------------------------------------------
// helpers
// ---------------------------------------------------------------------------
__device__ __forceinline__ uint32_t smem_u32(const void* p) {
    uint32_t a;
    asm("{ .reg .u64 t; cvta.to.shared.u64 t, %1; cvt.u32.u64 %0, t; }" : "=r"(a) : "l"(p));
    return a;
}
__device__ __forceinline__ uint32_t tf32u(float x) {
    uint32_t y; asm("cvt.rna.tf32.f32 %0, %1;" : "=r"(y) : "f"(x)); return y;
}
__device__ __forceinline__ float tf32f(float x) {
    return __uint_as_float(tf32u(x));
}
__device__ __forceinline__ void cp16(uint32_t dst, const void* src) {
    asm volatile("cp.async.cg.shared.global [%0], [%1], 16;" :: "r"(dst), "l"(src));
}
__device__ __forceinline__ void cp_commit() { asm volatile("cp.async.commit_group;"); }
__device__ __forceinline__ void cp_wait0() { asm volatile("cp.async.wait_group 0;" ::: "memory"); }
__device__ __forceinline__ void cp_wait1() { asm volatile("cp.async.wait_group 1;" ::: "memory"); }

// tf32 MMA; operands are raw fp32 bit patterns (HW truncates to tf32).
__device__ __forceinline__ void mma_tf32(float* c, const uint32_t* a, const uint32_t* b) {
    asm volatile(
        "mma.sync.aligned.m16n8k8.row.col.f32.tf32.tf32.f32 "
        "{%0,%1,%2,%3}, {%4,%5,%6,%7}, {%8,%9}, {%0,%1,%2,%3};"
        : "+f"(c[0]), "+f"(c[1]), "+f"(c[2]), "+f"(c[3])
        : "r"(a[0]), "r"(a[1]), "r"(a[2]), "r"(a[3]), "r"(b[0]), "r"(b[1]));
}

// ---------------------------------------------------------------------------
// TF32 tensor-core GEMM via mma.sync:
//   out[z,o,t] = sum_k W[o,k] * X[z,k,t] + bias[o] (+ R[z,o,t])
// CTA tile 128(o) x 128(t), K-tile 32, double-buffered cp.async.
// ---------------------------------------------------------------------------
#define WPAD 36
#define XPAD 136
#define GEMM_SMEM ((2 * 128 * WPAD + 2 * 32 * XPAD) * 4)

__global__ __launch_bounds__(256, 2) void mma_gemm(const float* __restrict__ W,
                                                   const float* __restrict__ X,
                                                   const float* __restrict__ bias,
                                                   const float* __restrict__ R,
                                                   float* __restrict__ out, int O) {
    extern __shared__ float sm[];
    float* sW = sm;                       // [2][128][WPAD]
    float* sX = sm + 2 * 128 * WPAD;      // [2][32][XPAD]

    const int tid = threadIdx.x;
    const int wid = tid >> 5, lane = tid & 31;
    const int gid = lane >> 2, tg = lane & 3;
    const int warp_m = (wid & 3) * 32, warp_n = (wid >> 2) * 64;

    const int t0 = blockIdx.x * 128, o0 = blockIdx.y * 128, z = blockIdx.z;
    const float* Xb = X + (size_t)z * 1024 * 1024;

    float c[2][8][4];
#pragma unroll
    for (int mt = 0; mt < 2; mt++)
#pragma unroll
        for (int nt = 0; nt < 8; nt++)
#pragma unroll
            for (int e = 0; e < 4; e++) c[mt][nt][e] = 0.f;

    uint32_t aW = smem_u32(sW), aX = smem_u32(sX);

    auto issue = [&](int buf, int kt) {
        const int k0 = kt * 32;
        uint32_t bW = aW + (uint32_t)(buf * 128 * WPAD * 4);
        uint32_t bX = aX + (uint32_t)(buf * 32 * XPAD * 4);
#pragma unroll
        for (int i = 0; i < 4; i++) {
            int id = tid * 4 + i;
            int row = id >> 3, kv = id & 7;
            cp16(bW + (uint32_t)((row * WPAD + kv * 4) * 4),
                 W + (size_t)(o0 + row) * 1024 + k0 + kv * 4);
        }
#pragma unroll
        for (int i = 0; i < 4; i++) {
            int id = tid * 4 + i;
            int krow = id >> 5, tv = id & 31;
            cp16(bX + (uint32_t)((krow * XPAD + tv * 4) * 4),
                 Xb + (size_t)(k0 + krow) * 1024 + t0 + tv * 4);
        }
        cp_commit();
    };

    issue(0, 0);

    for (int kt = 0; kt < 32; kt++) {
        const int buf = kt & 1;
        if (kt + 1 < 32) {
            issue(buf ^ 1, kt + 1);
            cp_wait1();
        } else {
            cp_wait0();
        }
        __syncthreads();

        const uint32_t* wb = (const uint32_t*)(sW + buf * 128 * WPAD);
        const uint32_t* xb = (const uint32_t*)(sX + buf * 32 * XPAD);

#pragma unroll
        for (int ks = 0; ks < 4; ks++) {
            const int kk = ks * 8;
            uint32_t af[2][4];
#pragma unroll
            for (int mt = 0; mt < 2; mt++) {
                const uint32_t* wr = wb + (warp_m + mt * 16 + gid) * WPAD + kk + tg;
                af[mt][0] = wr[0];
                af[mt][1] = wr[8 * WPAD];
                af[mt][2] = wr[4];
                af[mt][3] = wr[8 * WPAD + 4];
            }
            uint32_t bf[8][2];
#pragma unroll
            for (int nt = 0; nt < 8; nt++) {
                const uint32_t* xr = xb + (kk + tg) * XPAD + warp_n + nt * 8 + gid;
                bf[nt][0] = xr[0];
                bf[nt][1] = xr[4 * XPAD];
            }
#pragma unroll
            for (int mt = 0; mt < 2; mt++)
#pragma unroll
                for (int nt = 0; nt < 8; nt++)
                    mma_tf32(c[mt][nt], af[mt], bf[nt]);
        }
        __syncthreads();
    }

#pragma unroll
    for (int mt = 0; mt < 2; mt++) {
#pragma unroll
        for (int half = 0; half < 2; half++) {
            int o = o0 + warp_m + mt * 16 + gid + half * 8;
            float bv = bias[o];
            size_t rowbase = ((size_t)z * O + o) * 1024;
#pragma unroll
            for (int nt = 0; nt < 8; nt++) {
                int t = t0 + warp_n + nt * 8 + tg * 2;
                float2 v;
                v.x = c[mt][nt][half * 2 + 0] + bv;
                v.y = c[mt][nt][half * 2 + 1] + bv;
                if (R) {
                    float2 rr = *(const float2*)(R + rowbase + t);
                    v.x += rr.x; v.y += rr.y;
                }
                *(float2*)(out + rowbase + t) = v;
            }
        }
    }
}

// ---------------------------------------------------------------------------
// GroupNorm: one block per (batch, group); 1024 threads, float4 path.
// ---------------------------------------------------------------------------
__global__ __launch_bounds__(1024) void gn_kernel(const float* __restrict__ x,
                                                  const float* __restrict__ w,
                                                  const float* __restrict__ b,
                                                  float* __restrict__ xn) {
    int batch = blockIdx.x >> 5;
    int g = blockIdx.x & 31;
    const float4* xp = (const float4*)(x + ((size_t)batch * 1024 + g * 32) * 1024);
    float4* xo = (float4*)(xn + ((size_t)batch * 1024 + g * 32) * 1024);

    float s = 0.f, ss = 0.f;
#pragma unroll
    for (int r = 0; r < 8; r++) {
        float4 v = xp[r * 1024 + threadIdx.x];
        s += v.x + v.y + v.z + v.w;
        ss += v.x * v.x + v.y * v.y + v.z * v.z + v.w * v.w;
    }
#pragma unroll
    for (int o = 16; o; o >>= 1) {
        s  += __shfl_xor_sync(0xffffffffu, s, o);
        ss += __shfl_xor_sync(0xffffffffu, ss, o);
    }
    __shared__ float red[66];
    int warp = threadIdx.x >> 5, lane = threadIdx.x & 31;
    if (lane == 0) { red[warp] = s; red[warp + 32] = ss; }
    __syncthreads();
    if (threadIdx.x == 0) {
        float ts = 0.f, tss = 0.f;
#pragma unroll
        for (int i = 0; i < 32; i++) { ts += red[i]; tss += red[i + 32]; }
        float mu = ts * (1.f / 32768.f);
        float var = tss * (1.f / 32768.f) - mu * mu;
        red[64] = mu;
        red[65] = rsqrtf(var + 1e-5f);
    }
    __syncthreads();
    float mu = red[64], inv = red[65];
#pragma unroll
    for (int r = 0; r < 8; r++) {
        int idx4 = r * 1024 + threadIdx.x;
        int c = g * 32 + (idx4 >> 8);
        float sc = inv * w[c];
        float sh = b[c] - mu * sc;
        float4 v = xp[idx4];
        v.x = v.x * sc + sh; v.y = v.y * sc + sh;
        v.z = v.z * sc + sh; v.w = v.w * sc + sh;
        xo[idx4] = v;
    }
}

// ---------------------------------------------------------------------------
// Flash attention with tf32 mma.sync.
// Block = one (b,h) x 64-query tile. 256 threads, 8 warps (4 m x 2 n).
// ---------------------------------------------------------------------------
#define APITCH 72
#define KPITCH 68
#define ATTN_SMEM ((64 * APITCH * 3 + 64 * KPITCH + 256 + 256 + 192) * 4)

__global__ __launch_bounds__(256) void attn_mma(const float* __restrict__ qkv,
                                                float* __restrict__ out) {
    extern __shared__ float sm[];
    float* Qs   = sm;                    // [64][APITCH]
    float* Kt   = Qs + 64 * APITCH;      // [64][KPITCH]  j-major
    float* Vs   = Kt + 64 * KPITCH;      // [64][APITCH]
    float* Ss   = Vs + 64 * APITCH;      // [64][APITCH]  probs (tf32-rounded)
    float* pm   = Ss + 64 * APITCH;      // [4][64] partial max
    float* ps   = pm + 256;              // [4][64] partial sum
    float* marr = ps + 256;              // [64] running max
    float* lar  = marr + 64;             // [64] running sum
    float* aar  = lar + 64;              // [64] alpha

    const int bh = blockIdx.y;
    const int b = bh >> 4, h = bh & 15;
    const int t0 = blockIdx.x * 64;
    const float* qp = qkv + ((size_t)b * 3072 + h * 192) * 1024;
    const float* kp = qp + 64 * 1024;
    const float* vp = qp + 128 * 1024;

    const int tid = threadIdx.x, wid = tid >> 5, lane = tid & 31;
    const int gid = lane >> 2, tg = lane & 3;
    const int wq = wid & 3;
    const int warp_m = wq * 16;
    const int warp_n = (wid >> 2) * 32;

    // Q tile [c][i] (raw fp32; MMA truncates)
#pragma unroll
    for (int r = 0; r < 4; r++) {
        int id = r * 256 + tid;
        int cc = id >> 4, i4 = (id & 15) * 4;
        *(float4*)&Qs[cc * APITCH + i4] = *(const float4*)(qp + (size_t)cc * 1024 + t0 + i4);
    }
    if (tid < 64) { marr[tid] = -1e30f; lar[tid] = 0.f; }

    float o[4][4];
#pragma unroll
    for (int nt = 0; nt < 4; nt++)
#pragma unroll
        for (int e = 0; e < 4; e++) o[nt][e] = 0.f;

    for (int s0 = 0; s0 < 1024; s0 += 64) {
        __syncthreads();

        // K tile transposed: Kt[j][c]
#pragma unroll
        for (int r = 0; r < 16; r++) {
            int id = r * 256 + tid;
            int cc = id >> 6, j = id & 63;
            Kt[j * KPITCH + cc] = kp[(size_t)cc * 1024 + s0 + j];
        }
        // V tile natural: Vs[c][j]
#pragma unroll
        for (int r = 0; r < 4; r++) {
            int id = r * 256 + tid;
            int cc = id >> 4, j4 = (id & 15) * 4;
            *(float4*)&Vs[cc * APITCH + j4] = *(const float4*)(vp + (size_t)cc * 1024 + s0 + j4);
        }
        __syncthreads();

        // ---- S = Kt * Q ----
        float sc[4][4];
#pragma unroll
        for (int nt = 0; nt < 4; nt++)
#pragma unroll
            for (int e = 0; e < 4; e++) sc[nt][e] = 0.f;

#pragma unroll
        for (int ks = 0; ks < 8; ks++) {
            int kk = ks * 8;
            uint32_t a[4];
            a[0] = __float_as_uint(Kt[(warp_m + gid) * KPITCH + kk + tg]);
            a[1] = __float_as_uint(Kt[(warp_m + gid + 8) * KPITCH + kk + tg]);
            a[2] = __float_as_uint(Kt[(warp_m + gid) * KPITCH + kk + tg + 4]);
            a[3] = __float_as_uint(Kt[(warp_m + gid + 8) * KPITCH + kk + tg + 4]);
#pragma unroll
            for (int nt = 0; nt < 4; nt++) {
                uint32_t bb[2];
                bb[0] = __float_as_uint(Qs[(kk + tg) * APITCH + warp_n + nt * 8 + gid]);
                bb[1] = __float_as_uint(Qs[(kk + tg + 4) * APITCH + warp_n + nt * 8 + gid]);
                mma_tf32(sc[nt], a, bb);
            }
        }
#pragma unroll
        for (int nt = 0; nt < 4; nt++)
#pragma unroll
            for (int e = 0; e < 4; e++) sc[nt][e] *= 0.125f;

        // per-warp column max -> pm[wq][i]
#pragma unroll
        for (int nt = 0; nt < 4; nt++) {
            float m0 = fmaxf(sc[nt][0], sc[nt][2]);
            float m1 = fmaxf(sc[nt][1], sc[nt][3]);
#pragma unroll
            for (int mk = 4; mk <= 16; mk <<= 1) {
                m0 = fmaxf(m0, __shfl_xor_sync(0xffffffffu, m0, mk));
                m1 = fmaxf(m1, __shfl_xor_sync(0xffffffffu, m1, mk));
            }
            if (gid == 0) {
                int n = warp_n + nt * 8 + tg * 2;
                pm[wq * 64 + n] = m0;
                pm[wq * 64 + n + 1] = m1;
            }
        }
        __syncthreads();

        // phase A: exp + store probs + partial sums
#pragma unroll
        for (int nt = 0; nt < 4; nt++) {
            int n = warp_n + nt * 8 + tg * 2;
#pragma unroll
            for (int e = 0; e < 2; e++) {
                int i = n + e;
                float mn = fmaxf(fmaxf(fmaxf(pm[i], pm[64 + i]),
                                       fmaxf(pm[128 + i], pm[192 + i])), marr[i]);
                float p0 = tf32f(__expf(sc[nt][e] - mn));
                float p1 = tf32f(__expf(sc[nt][e + 2] - mn));
                Ss[(warp_m + gid) * APITCH + i] = p0;
                Ss[(warp_m + gid + 8) * APITCH + i] = p1;
                float su = p0 + p1;
#pragma unroll
                for (int mk = 4; mk <= 16; mk <<= 1)
                    su += __shfl_xor_sync(0xffffffffu, su, mk);
                if (gid == 0) ps[wq * 64 + i] = su;
            }
        }
        __syncthreads();

        // phase B: designated writers update running stats
        if (wq == 0 && gid == 0) {
#pragma unroll
            for (int nt = 0; nt < 4; nt++) {
#pragma unroll
                for (int e = 0; e < 2; e++) {
                    int i = warp_n + nt * 8 + tg * 2 + e;
                    float mo = marr[i];
                    float mn = fmaxf(fmaxf(fmaxf(pm[i], pm[64 + i]),
                                           fmaxf(pm[128 + i], pm[192 + i])), mo);
                    float al = __expf(mo - mn);
                    float st = ps[i] + ps[64 + i] + ps[128 + i] + ps[192 + i];
                    lar[i] = lar[i] * al + st;
                    marr[i] = mn;
                    aar[i] = al;
                }
            }
        }
        __syncthreads();

        // ---- O = V * P ----
#pragma unroll
        for (int nt = 0; nt < 4; nt++) {
            int n = warp_n + nt * 8 + tg * 2;
            float a0 = aar[n], a1 = aar[n + 1];
            o[nt][0] *= a0; o[nt][1] *= a1; o[nt][2] *= a0; o[nt][3] *= a1;
        }
#pragma unroll
        for (int ks = 0; ks < 8; ks++) {
            int kk = ks * 8;
            uint32_t a[4];
            a[0] = __float_as_uint(Vs[(warp_m + gid) * APITCH + kk + tg]);
            a[1] = __float_as_uint(Vs[(warp_m + gid + 8) * APITCH + kk + tg]);
            a[2] = __float_as_uint(Vs[(warp_m + gid) * APITCH + kk + tg + 4]);
            a[3] = __float_as_uint(Vs[(warp_m + gid + 8) * APITCH + kk + tg + 4]);
#pragma unroll
            for (int nt = 0; nt < 4; nt++) {
                uint32_t bb[2];
                bb[0] = __float_as_uint(Ss[(kk + tg) * APITCH + warp_n + nt * 8 + gid]);
                bb[1] = __float_as_uint(Ss[(kk + tg + 4) * APITCH + warp_n + nt * 8 + gid]);
                mma_tf32(o[nt], a, bb);
            }
        }
    }
    __syncthreads();

    // normalize + write Ot[c][i] to attn[b, h*64+c, t0+i]
#pragma unroll
    for (int nt = 0; nt < 4; nt++) {
        int n = warp_n + nt * 8 + tg * 2;
        float li0 = 1.f / lar[n], li1 = 1.f / lar[n + 1];
        size_t base0 = ((size_t)b * 1024 + h * 64 + warp_m + gid) * 1024 + t0 + n;
        float2 v0 = { o[nt][0] * li0, o[nt][1] * li1 };
        *(float2*)(out + base0) = v0;
        float2 v1 = { o[nt][2] * li0, o[nt][3] * li1 };
        *(float2*)(out + base0 + 8 * 1024) = v1;
    }
}

// ---------------------------------------------------------------------------
extern "C" void kernel_launch(void* const* d_in, const int* in_sizes, int n_in,
                              void* d_out, int out_size) {
    const float* x      = (const float*)d_in[0];
    const float* nw     = (const float*)d_in[1];
    const float* nb     = (const float*)d_in[2];
    const float* qkv_w  = (const float*)d_in[3];
    const float* qkv_b  = (const float*)d_in[4];
    const float* proj_w = (const float*)d_in[5];
    const float* proj_b = (const float*)d_in[6];
    float* out = (float*)d_out;

    float *xn, *qkv, *attn;
    cudaGetSymbolAddress((void**)&xn,   g_xn);
    cudaGetSymbolAddress((void**)&qkv,  g_qkv);
    cudaGetSymbolAddress((void**)&attn, g_attn);

    // 1. GroupNorm
    gn_kernel<<<128, 1024>>>(x, nw, nb, xn);

    // 2. QKV projection (tf32 mma.sync)
    cudaFuncSetAttribute(mma_gemm, cudaFuncAttributeMaxDynamicSharedMemorySize, GEMM_SMEM);
    mma_gemm<<<dim3(8, 24, 4), 256, GEMM_SMEM>>>(qkv_w, xn, qkv_b, nullptr, qkv, 3072);

    // 3. Attention (tf32 mma.sync flash)
    cudaFuncSetAttribute(attn_mma, cudaFuncAttributeMaxDynamicSharedMemorySize, ATTN_SMEM);
    attn_mma<<<dim3(16, 64), 256, ATTN_SMEM>>>(qkv, attn);

    // 4. Output projection + bias + residual (tf32 mma.sync)
    mma_gemm<<<dim3(8, 8, 4), 256, GEMM_SMEM>>>(proj_w, attn, proj_b, x, out, 1024);
}